// round 11
// baseline (speedup 1.0000x reference)
#include <cuda_runtime.h>
#include <cuda_fp16.h>
#include <cstdint>

#define MDIM 1024
#define RANK 128
#define NBATCH 8
#define SEQ 512
#define NROWS (NBATCH * SEQ)          // 4096
#define KSPLIT 2
#define KS (MDIM / KSPLIT)            // 512
#define KC 64                         // k per smem chunk (gemm)
#define CHUNKS (KS / KC)              // 8

// Scratch (static __device__ globals; no allocations allowed).
__device__ float g_Tp[KSPLIT][NROWS * RANK];   // K-split partials, 4 MB
__device__ float g_norm[NROWS];                // row squared norms (fp32 exact)
__device__ __half g_Bhi[RANK * MDIM];          // B^T hi: [n][k] fp16
__device__ __half g_Blo[RANK * MDIM];          // B^T lo: [n][k] fp16 (residual)
__device__ __half g_Th[NROWS * RANK];          // T: [row][k] fp16

// ---------------- helpers ----------------
__device__ __forceinline__ uint32_t sm2u32(const void* p) {
    uint32_t a;
    asm("{ .reg .u64 t; cvta.to.shared.u64 t, %1; cvt.u32.u64 %0, t; }"
        : "=r"(a) : "l"(p));
    return a;
}
#define LDMX4(r, addr) \
    asm volatile("ldmatrix.sync.aligned.m8n8.x4.shared.b16 {%0,%1,%2,%3}, [%4];" \
        : "=r"((r)[0]), "=r"((r)[1]), "=r"((r)[2]), "=r"((r)[3]) : "r"(addr))

__device__ __forceinline__ void mma_f16(float* c, const uint32_t* a,
                                        uint32_t b0, uint32_t b1) {
    asm volatile(
        "mma.sync.aligned.m16n8k16.row.col.f32.f16.f16.f32 "
        "{%0,%1,%2,%3}, {%4,%5,%6,%7}, {%8,%9}, {%0,%1,%2,%3};"
        : "+f"(c[0]), "+f"(c[1]), "+f"(c[2]), "+f"(c[3])
        : "r"(a[0]), "r"(a[1]), "r"(a[2]), "r"(a[3]), "r"(b0), "r"(b1));
}

// ---------------------------------------------------------------------------
// Kernel 0: transpose+split proj [1024,128] fp32 -> g_Bhi/g_Blo [128][1024] fp16
// ---------------------------------------------------------------------------
__global__ void convertB_kernel(const float* __restrict__ proj)
{
    __shared__ float tile[32][33];
    const int tx = threadIdx.x, ty = threadIdx.y;      // (32,8)
    const int k0 = blockIdx.x * 32, n0 = blockIdx.y * 32;
    #pragma unroll
    for (int i = 0; i < 4; i++)
        tile[ty + 8 * i][tx] = proj[(size_t)(k0 + ty + 8 * i) * RANK + n0 + tx];
    __syncthreads();
    #pragma unroll
    for (int i = 0; i < 4; i++) {
        int n = n0 + ty + 8 * i, k = k0 + tx;
        float v = tile[tx][ty + 8 * i];
        __half h = __float2half_rn(v);
        __half l = __float2half_rn(v - __half2float(h));
        g_Bhi[(size_t)n * MDIM + k] = h;
        g_Blo[(size_t)n * MDIM + k] = l;
    }
}

// ---------------------------------------------------------------------------
// Kernel 1: mma.sync fp16 GEMM: acc(f32) += A(fp16) * (Bhi + Blo).
// grid (KSPLIT=2, 64 m-tiles, 2 n-tiles) = 256 CTAs, 256 thr (8 warps).
// CTA: M=64, N=64, K=KS(512) in 8 chunks of 64. Warp grid 4(m)x2(n), tile 16x32.
// smem rows padded to 144B; total 27.6 KB -> multiple CTAs/SM.
// ---------------------------------------------------------------------------
#define AH_OFF 0
#define BH_OFF 9216
#define BL_OFF 18432
#define SMEM_BYTES 27648

__global__ void __launch_bounds__(256) mma_gemm_kernel(const float* __restrict__ A)
{
    extern __shared__ char dsm[];
    const int tid  = threadIdx.x;
    const int wid  = tid >> 5, lane = tid & 31;
    const int split = blockIdx.x;
    const int mb    = blockIdx.y * 64;
    const int nb0   = blockIdx.z * 64;
    const int kbase = split * KS;

    const int warp_m = (wid & 3) * 16;
    const int warp_n = (wid >> 2) * 32;

    const uint32_t smem = sm2u32(dsm);
    const uint32_t a_off = (uint32_t)(warp_m + (lane & 15)) * 144 + (lane >> 4) * 16;
    const uint32_t aaddr = smem + AH_OFF + a_off;
    const uint32_t b_noff = ((lane >> 3) & 1) * 8 + (lane & 7);
    const uint32_t b_off  = (uint32_t)(warp_n + b_noff) * 144 + (lane >> 4) * 16;
    const uint32_t baddr_h = smem + BH_OFF + b_off;
    const uint32_t baddr_l = smem + BL_OFF + b_off;

    float acc[4][4];
    #pragma unroll
    for (int i = 0; i < 4; i++)
        #pragma unroll
        for (int j = 0; j < 4; j++) acc[i][j] = 0.0f;

    for (int c = 0; c < CHUNKS; c++) {
        if (c) __syncthreads();

        // A chunk [64][64] fp32 -> fp16 into smem (1024 float4, 4/thread)
        #pragma unroll
        for (int t = 0; t < 4; t++) {
            int idx = tid + t * 256;
            int r = idx >> 4, k4 = idx & 15;
            float4 v = *(const float4*)&A[(size_t)(mb + r) * MDIM + kbase + c * KC + k4 * 4];
            union { __half2 h2[2]; unsigned long long u; } ph;
            ph.h2[0] = __halves2half2(__float2half_rn(v.x), __float2half_rn(v.y));
            ph.h2[1] = __halves2half2(__float2half_rn(v.z), __float2half_rn(v.w));
            *(unsigned long long*)(dsm + AH_OFF + r * 144 + k4 * 8) = ph.u;
        }
        // B chunk [64 n][64 k] fp16 hi/lo (512 uint4 each, 2/thread each)
        #pragma unroll
        for (int t = 0; t < 2; t++) {
            int idx = tid + t * 256;
            int n = idx >> 3, g = idx & 7;
            size_t src = (size_t)(nb0 + n) * MDIM + kbase + c * KC + g * 8;
            *(uint4*)(dsm + BH_OFF + n * 144 + g * 16) = *(const uint4*)&g_Bhi[src];
            *(uint4*)(dsm + BL_OFF + n * 144 + g * 16) = *(const uint4*)&g_Blo[src];
        }
        __syncthreads();

        #pragma unroll
        for (int kk = 0; kk < 4; kk++) {
            uint32_t ah[4];
            LDMX4(ah, aaddr + kk * 32);
            #pragma unroll
            for (int nn = 0; nn < 2; nn++) {
                uint32_t bh[4], bl[4];
                LDMX4(bh, baddr_h + nn * 16 * 144 + kk * 32);
                LDMX4(bl, baddr_l + nn * 16 * 144 + kk * 32);
                float* c0 = acc[nn * 2];
                float* c1 = acc[nn * 2 + 1];
                mma_f16(c0, ah, bh[0], bh[2]);
                mma_f16(c0, ah, bl[0], bl[2]);
                mma_f16(c1, ah, bh[1], bh[3]);
                mma_f16(c1, ah, bl[1], bl[3]);
            }
        }
    }

    float* __restrict__ P = g_Tp[split];
    const int m0 = mb + warp_m + (lane >> 2);
    #pragma unroll
    for (int ch = 0; ch < 4; ch++) {
        int n = nb0 + warp_n + ch * 8 + (lane & 3) * 2;
        *(float2*)&P[(size_t)m0 * RANK + n] = make_float2(acc[ch][0], acc[ch][1]);
        *(float2*)&P[(size_t)(m0 + 8) * RANK + n] = make_float2(acc[ch][2], acc[ch][3]);
    }
}

// ---------------------------------------------------------------------------
// Kernel 2: combine 2 K-split partials -> fp16 T + fp32 per-row squared norms.
// ---------------------------------------------------------------------------
__global__ void __launch_bounds__(256) combine_kernel()
{
    int idx = blockIdx.x * 256 + threadIdx.x;      // float4 index
    const float4* p0 = (const float4*)g_Tp[0];
    const float4* p1 = (const float4*)g_Tp[1];
    float4 a = p0[idx], b = p1[idx];
    float4 v;
    v.x = a.x + b.x;
    v.y = a.y + b.y;
    v.z = a.z + b.z;
    v.w = a.w + b.w;

    union { __half2 h2[2]; uint2 u; } ph;
    ph.h2[0] = __halves2half2(__float2half_rn(v.x), __float2half_rn(v.y));
    ph.h2[1] = __halves2half2(__float2half_rn(v.z), __float2half_rn(v.w));
    *(uint2*)&g_Th[(size_t)idx * 4] = ph.u;

    float sq = v.x * v.x + v.y * v.y + v.z * v.z + v.w * v.w;
    #pragma unroll
    for (int off = 16; off > 0; off >>= 1)
        sq += __shfl_down_sync(0xffffffffu, sq, off);
    if ((threadIdx.x & 31) == 0)
        g_norm[idx >> 5] = sq;                     // 32 float4 per row
}

// ---------------------------------------------------------------------------
// Kernel 3: pdist via single-pass fp16 mma.sync Gram.
// CTA: 64(i) x 64(j) tile, full K=128 in smem. grid (8,8,8)=512 CTAs, 256 thr.
// Warp grid 2(m)x4(n); warp tile 32x16.
// d(i,j) = n_i + n_j - 2*(I·J); diag forced to 0.
// smem rows 272B (272 % 128 = 16 -> ldmatrix conflict-free); 34.8 KB total.
// ---------------------------------------------------------------------------
#define PD_I 0
#define PD_J 17408
#define PD_SMEM 34816
#define PD_STR 272

__global__ void __launch_bounds__(256) pdist_mma_kernel(float* __restrict__ out)
{
    extern __shared__ char dsm[];
    const int tid  = threadIdx.x;
    const int wid  = tid >> 5, lane = tid & 31;
    const int bj = blockIdx.x, bi = blockIdx.y, b = blockIdx.z;
    const int i0 = bi * 64, j0 = bj * 64;
    const bool diag = (bi == bj);

    const __half* __restrict__ TH = g_Th + (size_t)b * SEQ * RANK;

    // Stage I (and J if off-diagonal): 64 rows x 128 k fp16 = 1024 uint4 each.
    #pragma unroll
    for (int t = 0; t < 4; t++) {
        int idx = tid + t * 256;          // 0..1023
        int r = idx >> 4, g = idx & 15;
        size_t si = (size_t)(i0 + r) * RANK + g * 8;
        *(uint4*)(dsm + PD_I + r * PD_STR + g * 16) = *(const uint4*)&TH[si];
        if (!diag) {
            size_t sj = (size_t)(j0 + r) * RANK + g * 8;
            *(uint4*)(dsm + PD_J + r * PD_STR + g * 16) = *(const uint4*)&TH[sj];
        }
    }
    __syncthreads();

    const int warp_m = (wid & 1) * 32;
    const int warp_n = (wid >> 1) * 16;
    const uint32_t smem = sm2u32(dsm);

    const uint32_t ia_off = (uint32_t)(warp_m + (lane & 15)) * PD_STR + (lane >> 4) * 16;
    const uint32_t iaddr = smem + PD_I + ia_off;
    const uint32_t j_noff = ((lane >> 3) & 1) * 8 + (lane & 7);
    const uint32_t ja_off = (uint32_t)(warp_n + j_noff) * PD_STR + (lane >> 4) * 16;
    const uint32_t jaddr = smem + (diag ? PD_I : PD_J) + ja_off;

    float acc[2][2][4];
    #pragma unroll
    for (int mf = 0; mf < 2; mf++)
        #pragma unroll
        for (int i = 0; i < 2; i++)
            #pragma unroll
            for (int j = 0; j < 4; j++) acc[mf][i][j] = 0.0f;

    #pragma unroll
    for (int kk = 0; kk < 8; kk++) {
        uint32_t ih[2][4], jh[4];
        LDMX4(ih[0], iaddr + kk * 32);
        LDMX4(ih[1], iaddr + 16 * PD_STR + kk * 32);
        LDMX4(jh, jaddr + kk * 32);
        #pragma unroll
        for (int mf = 0; mf < 2; mf++) {
            mma_f16(acc[mf][0], ih[mf], jh[0], jh[2]);
            mma_f16(acc[mf][1], ih[mf], jh[1], jh[3]);
        }
    }

    // Epilogue: d = n_i + n_j - 2*dot; exact 0 on diagonal.
    const float* __restrict__ nb = g_norm + (size_t)b * SEQ;
    float* __restrict__ ob = out + (size_t)b * SEQ * SEQ;
    #pragma unroll
    for (int mf = 0; mf < 2; mf++) {
        int gi = i0 + warp_m + mf * 16 + (lane >> 2);
        float ni0 = nb[gi], ni1 = nb[gi + 8];
        #pragma unroll
        for (int ch = 0; ch < 2; ch++) {
            int gj = j0 + warp_n + ch * 8 + (lane & 3) * 2;
            float nj0 = nb[gj], nj1 = nb[gj + 1];
            float* a = acc[mf][ch];
            float v00 = ni0 + nj0 - 2.0f * a[0];
            float v01 = ni0 + nj1 - 2.0f * a[1];
            float v10 = ni1 + nj0 - 2.0f * a[2];
            float v11 = ni1 + nj1 - 2.0f * a[3];
            if (diag) {
                if (gi == gj) v00 = 0.0f;
                if (gi == gj + 1) v01 = 0.0f;
                if (gi + 8 == gj) v10 = 0.0f;
                if (gi + 8 == gj + 1) v11 = 0.0f;
            }
            *(float2*)&ob[(size_t)gi * SEQ + gj] = make_float2(v00, v01);
            *(float2*)&ob[(size_t)(gi + 8) * SEQ + gj] = make_float2(v10, v11);
        }
    }
}

extern "C" void kernel_launch(void* const* d_in, const int* in_sizes, int n_in,
                              void* d_out, int out_size)
{
    const float* batch = (const float*)d_in[0];   // [8,512,1024]
    const float* proj  = (const float*)d_in[1];   // [1024,128]
    float* out = (float*)d_out;                   // [8,512,512]

    convertB_kernel<<<dim3(MDIM / 32, RANK / 32), dim3(32, 8)>>>(proj);
    mma_gemm_kernel<<<dim3(KSPLIT, NROWS / 64, 2), 256, SMEM_BYTES>>>(batch);
    combine_kernel<<<NROWS * RANK / 4 / 256, 256>>>();
    pdist_mma_kernel<<<dim3(8, 8, 8), 256, PD_SMEM>>>(out);
}

// round 12
// speedup vs baseline: 1.0906x; 1.0906x over previous
#include <cuda_runtime.h>
#include <cuda_fp16.h>
#include <cstdint>

#define MDIM 1024
#define RANK 128
#define NBATCH 8
#define SEQ 512
#define NROWS (NBATCH * SEQ)          // 4096
#define KSPLIT 4
#define KS (MDIM / KSPLIT)            // 256
#define KC 64                         // k per smem chunk (gemm)
#define CHUNKS (KS / KC)              // 4

// Scratch (static __device__ globals; no allocations allowed).
__device__ float g_Tp[KSPLIT][NROWS * RANK];   // K-split partials, 8 MB
__device__ float g_norm[NROWS];                // row squared norms (fp32 exact)
__device__ __half g_Bhi[RANK * MDIM];          // B^T hi: [n][k] fp16
__device__ __half g_Blo[RANK * MDIM];          // B^T lo: [n][k] fp16 (residual)
__device__ __half g_Th[NROWS * RANK];          // T: [row][k] fp16

// ---------------- helpers ----------------
__device__ __forceinline__ uint32_t sm2u32(const void* p) {
    uint32_t a;
    asm("{ .reg .u64 t; cvta.to.shared.u64 t, %1; cvt.u32.u64 %0, t; }"
        : "=r"(a) : "l"(p));
    return a;
}
#define LDMX4(r, addr) \
    asm volatile("ldmatrix.sync.aligned.m8n8.x4.shared.b16 {%0,%1,%2,%3}, [%4];" \
        : "=r"((r)[0]), "=r"((r)[1]), "=r"((r)[2]), "=r"((r)[3]) : "r"(addr))

__device__ __forceinline__ void mma_f16(float* c, const uint32_t* a,
                                        uint32_t b0, uint32_t b1) {
    asm volatile(
        "mma.sync.aligned.m16n8k16.row.col.f32.f16.f16.f32 "
        "{%0,%1,%2,%3}, {%4,%5,%6,%7}, {%8,%9}, {%0,%1,%2,%3};"
        : "+f"(c[0]), "+f"(c[1]), "+f"(c[2]), "+f"(c[3])
        : "r"(a[0]), "r"(a[1]), "r"(a[2]), "r"(a[3]), "r"(b0), "r"(b1));
}

// ---------------------------------------------------------------------------
// Kernel 0: transpose+split proj [1024,128] fp32 -> g_Bhi/g_Blo [128][1024] fp16
// ---------------------------------------------------------------------------
__global__ void convertB_kernel(const float* __restrict__ proj)
{
    __shared__ float tile[32][33];
    const int tx = threadIdx.x, ty = threadIdx.y;      // (32,8)
    const int k0 = blockIdx.x * 32, n0 = blockIdx.y * 32;
    #pragma unroll
    for (int i = 0; i < 4; i++)
        tile[ty + 8 * i][tx] = proj[(size_t)(k0 + ty + 8 * i) * RANK + n0 + tx];
    __syncthreads();
    #pragma unroll
    for (int i = 0; i < 4; i++) {
        int n = n0 + ty + 8 * i, k = k0 + tx;
        float v = tile[tx][ty + 8 * i];
        __half h = __float2half_rn(v);
        __half l = __float2half_rn(v - __half2float(h));
        g_Bhi[(size_t)n * MDIM + k] = h;
        g_Blo[(size_t)n * MDIM + k] = l;
    }
}

// ---------------------------------------------------------------------------
// Kernel 1: mma.sync fp16 GEMM: acc(f32) += A(fp16) * (Bhi + Blo).
// grid (KSPLIT, 64), 512 thr (16 warps). CTA: M=64, N=128, K=KS(256), 4 chunks.
// Warp grid 4(m)x4(n), warp tile 16x32. smem rows padded to 144B.  (R10 config)
// ---------------------------------------------------------------------------
#define AH_OFF 0
#define BH_OFF 9216
#define BL_OFF 27648
#define SMEM_BYTES 46080

__global__ void __launch_bounds__(512) mma_gemm_kernel(const float* __restrict__ A)
{
    extern __shared__ char dsm[];
    const int tid  = threadIdx.x;
    const int wid  = tid >> 5, lane = tid & 31;
    const int split = blockIdx.x;
    const int mb    = blockIdx.y * 64;
    const int kbase = split * KS;

    const int warp_m = (wid & 3) * 16;
    const int warp_n = (wid >> 2) * 32;

    const uint32_t smem = sm2u32(dsm);
    const uint32_t a_off = (uint32_t)(warp_m + (lane & 15)) * 144 + (lane >> 4) * 16;
    const uint32_t aaddr = smem + AH_OFF + a_off;
    const uint32_t b_noff = ((lane >> 3) & 1) * 8 + (lane & 7);
    const uint32_t b_off  = (uint32_t)(warp_n + b_noff) * 144 + (lane >> 4) * 16;
    const uint32_t baddr_h = smem + BH_OFF + b_off;
    const uint32_t baddr_l = smem + BL_OFF + b_off;

    float acc[4][4];
    #pragma unroll
    for (int i = 0; i < 4; i++)
        #pragma unroll
        for (int j = 0; j < 4; j++) acc[i][j] = 0.0f;

    for (int c = 0; c < CHUNKS; c++) {
        if (c) __syncthreads();

        // A chunk [64][64] fp32 -> fp16 into smem (1024 float4, 2/thread)
        #pragma unroll
        for (int t = 0; t < 2; t++) {
            int idx = tid + t * 512;
            int r = idx >> 4, k4 = idx & 15;
            float4 v = *(const float4*)&A[(size_t)(mb + r) * MDIM + kbase + c * KC + k4 * 4];
            union { __half2 h2[2]; unsigned long long u; } ph;
            ph.h2[0] = __halves2half2(__float2half_rn(v.x), __float2half_rn(v.y));
            ph.h2[1] = __halves2half2(__float2half_rn(v.z), __float2half_rn(v.w));
            *(unsigned long long*)(dsm + AH_OFF + r * 144 + k4 * 8) = ph.u;
        }
        // B chunk [128][64] fp16 hi/lo (1024 uint4, 2/thread)
        #pragma unroll
        for (int t = 0; t < 2; t++) {
            int idx = tid + t * 512;
            int n = idx >> 3, g = idx & 7;
            size_t src = (size_t)n * MDIM + kbase + c * KC + g * 8;
            *(uint4*)(dsm + BH_OFF + n * 144 + g * 16) = *(const uint4*)&g_Bhi[src];
            *(uint4*)(dsm + BL_OFF + n * 144 + g * 16) = *(const uint4*)&g_Blo[src];
        }
        __syncthreads();

        #pragma unroll
        for (int kk = 0; kk < 4; kk++) {
            uint32_t ah[4];
            LDMX4(ah, aaddr + kk * 32);
            #pragma unroll
            for (int nn = 0; nn < 2; nn++) {
                uint32_t bh[4], bl[4];
                LDMX4(bh, baddr_h + nn * 16 * 144 + kk * 32);
                LDMX4(bl, baddr_l + nn * 16 * 144 + kk * 32);
                float* c0 = acc[nn * 2];
                float* c1 = acc[nn * 2 + 1];
                mma_f16(c0, ah, bh[0], bh[2]);
                mma_f16(c0, ah, bl[0], bl[2]);
                mma_f16(c1, ah, bh[1], bh[3]);
                mma_f16(c1, ah, bl[1], bl[3]);
            }
        }
    }

    float* __restrict__ P = g_Tp[split];
    const int m0 = mb + warp_m + (lane >> 2);
    #pragma unroll
    for (int ch = 0; ch < 4; ch++) {
        int n = warp_n + ch * 8 + (lane & 3) * 2;
        *(float2*)&P[(size_t)m0 * RANK + n] = make_float2(acc[ch][0], acc[ch][1]);
        *(float2*)&P[(size_t)(m0 + 8) * RANK + n] = make_float2(acc[ch][2], acc[ch][3]);
    }
}

// ---------------------------------------------------------------------------
// Kernel 2: combine 4 K-split partials -> fp16 T + fp32 per-row squared norms.
// ---------------------------------------------------------------------------
__global__ void __launch_bounds__(256) combine_kernel()
{
    int idx = blockIdx.x * 256 + threadIdx.x;      // float4 index
    const float4* p0 = (const float4*)g_Tp[0];
    const float4* p1 = (const float4*)g_Tp[1];
    const float4* p2 = (const float4*)g_Tp[2];
    const float4* p3 = (const float4*)g_Tp[3];
    float4 a = p0[idx], b = p1[idx], c = p2[idx], d = p3[idx];
    float4 v;
    v.x = a.x + b.x + c.x + d.x;
    v.y = a.y + b.y + c.y + d.y;
    v.z = a.z + b.z + c.z + d.z;
    v.w = a.w + b.w + c.w + d.w;

    union { __half2 h2[2]; uint2 u; } ph;
    ph.h2[0] = __halves2half2(__float2half_rn(v.x), __float2half_rn(v.y));
    ph.h2[1] = __halves2half2(__float2half_rn(v.z), __float2half_rn(v.w));
    *(uint2*)&g_Th[(size_t)idx * 4] = ph.u;

    float sq = v.x * v.x + v.y * v.y + v.z * v.z + v.w * v.w;
    #pragma unroll
    for (int off = 16; off > 0; off >>= 1)
        sq += __shfl_down_sync(0xffffffffu, sq, off);
    if ((threadIdx.x & 31) == 0)
        g_norm[idx >> 5] = sq;                     // 32 float4 per row
}

// ---------------------------------------------------------------------------
// Kernel 3: pdist via single-pass fp16 mma.sync Gram.
// CTA: 128(i) x 64(j) tile, full K=128 in smem. grid (8,4,8)=256 CTAs, 256 thr.
// Warp grid 4(m)x2(n); warp tile 32x32.  52 KB smem -> 2 CTAs/SM co-resident.
// d(i,j) = n_i + n_j - 2*(I·J); diag forced to 0 via index check.
// smem rows 272B (272 % 128 = 16 -> ldmatrix conflict-free).
// ---------------------------------------------------------------------------
#define PD_I 0
#define PD_J 34816
#define PD_SMEM 52224
#define PD_STR 272

__global__ void __launch_bounds__(256) pdist_mma_kernel(float* __restrict__ out)
{
    extern __shared__ char dsm[];
    const int tid  = threadIdx.x;
    const int wid  = tid >> 5, lane = tid & 31;
    const int bj = blockIdx.x, bi = blockIdx.y, b = blockIdx.z;
    const int i0 = bi * 128, j0 = bj * 64;

    const __half* __restrict__ TH = g_Th + (size_t)b * SEQ * RANK;

    // Stage I: 128 rows x 128 k fp16 (2048 uint4, 8/thread)
    #pragma unroll
    for (int t = 0; t < 8; t++) {
        int idx = tid + t * 256;
        int r = idx >> 4, g = idx & 15;
        size_t si = (size_t)(i0 + r) * RANK + g * 8;
        *(uint4*)(dsm + PD_I + r * PD_STR + g * 16) = *(const uint4*)&TH[si];
    }
    // Stage J: 64 rows x 128 k fp16 (1024 uint4, 4/thread)
    #pragma unroll
    for (int t = 0; t < 4; t++) {
        int idx = tid + t * 256;
        int r = idx >> 4, g = idx & 15;
        size_t sj = (size_t)(j0 + r) * RANK + g * 8;
        *(uint4*)(dsm + PD_J + r * PD_STR + g * 16) = *(const uint4*)&TH[sj];
    }
    __syncthreads();

    const int warp_m = (wid & 3) * 32;
    const int warp_n = (wid >> 2) * 32;
    const uint32_t smem = sm2u32(dsm);

    const uint32_t ia_off = (uint32_t)(warp_m + (lane & 15)) * PD_STR + (lane >> 4) * 16;
    const uint32_t iaddr = smem + PD_I + ia_off;
    const uint32_t j_noff = ((lane >> 3) & 1) * 8 + (lane & 7);
    const uint32_t ja_off = (uint32_t)(warp_n + j_noff) * PD_STR + (lane >> 4) * 16;
    const uint32_t jaddr = smem + PD_J + ja_off;

    float acc[2][4][4];
    #pragma unroll
    for (int mf = 0; mf < 2; mf++)
        #pragma unroll
        for (int i = 0; i < 4; i++)
            #pragma unroll
            for (int j = 0; j < 4; j++) acc[mf][i][j] = 0.0f;

    #pragma unroll
    for (int kk = 0; kk < 8; kk++) {
        uint32_t ih[2][4];
        LDMX4(ih[0], iaddr + kk * 32);
        LDMX4(ih[1], iaddr + 16 * PD_STR + kk * 32);
        #pragma unroll
        for (int nn = 0; nn < 2; nn++) {
            uint32_t jh[4];
            LDMX4(jh, jaddr + nn * 16 * PD_STR + kk * 32);
            #pragma unroll
            for (int mf = 0; mf < 2; mf++) {
                float* c0 = acc[mf][nn * 2];
                float* c1 = acc[mf][nn * 2 + 1];
                mma_f16(c0, ih[mf], jh[0], jh[2]);
                mma_f16(c1, ih[mf], jh[1], jh[3]);
            }
        }
    }

    // Epilogue: d = n_i + n_j - 2*dot; exact 0 on diagonal.
    const float* __restrict__ nb = g_norm + (size_t)b * SEQ;
    float* __restrict__ ob = out + (size_t)b * SEQ * SEQ;
    #pragma unroll
    for (int mf = 0; mf < 2; mf++) {
        int gi = i0 + warp_m + mf * 16 + (lane >> 2);
        float ni0 = nb[gi], ni1 = nb[gi + 8];
        #pragma unroll
        for (int ch = 0; ch < 4; ch++) {
            int gj = j0 + warp_n + ch * 8 + (lane & 3) * 2;
            float nj0 = nb[gj], nj1 = nb[gj + 1];
            float* a = acc[mf][ch];
            float v00 = ni0 + nj0 - 2.0f * a[0];
            float v01 = ni0 + nj1 - 2.0f * a[1];
            float v10 = ni1 + nj0 - 2.0f * a[2];
            float v11 = ni1 + nj1 - 2.0f * a[3];
            if (gi == gj) v00 = 0.0f;
            if (gi == gj + 1) v01 = 0.0f;
            if (gi + 8 == gj) v10 = 0.0f;
            if (gi + 8 == gj + 1) v11 = 0.0f;
            *(float2*)&ob[(size_t)gi * SEQ + gj] = make_float2(v00, v01);
            *(float2*)&ob[(size_t)(gi + 8) * SEQ + gj] = make_float2(v10, v11);
        }
    }
}

extern "C" void kernel_launch(void* const* d_in, const int* in_sizes, int n_in,
                              void* d_out, int out_size)
{
    const float* batch = (const float*)d_in[0];   // [8,512,1024]
    const float* proj  = (const float*)d_in[1];   // [1024,128]
    float* out = (float*)d_out;                   // [8,512,512]

    // Idempotent; first call happens on the correctness run (outside capture).
    cudaFuncSetAttribute(pdist_mma_kernel,
                         cudaFuncAttributeMaxDynamicSharedMemorySize, PD_SMEM);

    convertB_kernel<<<dim3(MDIM / 32, RANK / 32), dim3(32, 8)>>>(proj);
    mma_gemm_kernel<<<dim3(KSPLIT, NROWS / 64), 512, SMEM_BYTES>>>(batch);
    combine_kernel<<<NROWS * RANK / 4 / 256, 256>>>();
    pdist_mma_kernel<<<dim3(SEQ / 64, SEQ / 128, NBATCH), 256, PD_SMEM>>>(out);
}